// round 4
// baseline (speedup 1.0000x reference)
#include <cuda_runtime.h>

#define NBATCH 4
#define CCH 256
#define FH 100
#define FW 152
#define HW (FH*FW)           // 15200
#define FWC (FW*CCH)         // 38912
#define NROI 4000
#define HALF_CH 128
#define HALF_OUT (HALF_CH*49)      // 6272 floats, linear 16B-aligned region
#define SMEM_BYTES (HALF_OUT*4)    // 25088 B

// NHWC scratch (device global: allocation-free scratch per harness rules)
__device__ float g_nhwc[NBATCH * HW * CCH];

// ---------------------------------------------------------------------------
// Kernel A: NCHW -> NHWC transpose (per batch: [256, 15200] transpose),
// 32x32 smem tiles, both phases fully coalesced.
// ---------------------------------------------------------------------------
__global__ void transpose_kernel(const float* __restrict__ in) {
    __shared__ float tile[32][33];
    int b   = blockIdx.z;
    int hw0 = blockIdx.x * 32;
    int c0  = blockIdx.y * 32;

    const float* src = in + (size_t)b * CCH * HW;
    #pragma unroll
    for (int r = threadIdx.y; r < 32; r += 8)
        tile[r][threadIdx.x] = src[(size_t)(c0 + r) * HW + (hw0 + threadIdx.x)];
    __syncthreads();

    float* dst = g_nhwc + (size_t)b * HW * CCH;
    #pragma unroll
    for (int r = threadIdx.y; r < 32; r += 8)
        dst[(size_t)(hw0 + r) * CCH + (c0 + threadIdx.x)] = tile[threadIdx.x][r];
}

// ---------------------------------------------------------------------------
// Row-group body (float2: 2 consecutive channels per thread). Gathers NR
// consecutive sample rows starting at i0, rolling 2x2 pool into smem stage.
// ---------------------------------------------------------------------------
template<int NR>
__device__ __forceinline__ void process_rows2(
    int i0, const float* __restrict__ fbase, int c0,
    const int* s_ws, const int* s_hs,
    const float* s_wf, const float* s_hf,
    const float* s_wm, const float* s_hm,
    float* s_out)
{
    float2 prev[8], cur[8];
    #pragma unroll
    for (int k = 0; k < NR; ++k) {
        const int i = i0 + k;
        const float* r0 = fbase + s_hs[i] * FWC;
        const float hf = s_hf[i];
        const float hm = s_hm[i];

        #pragma unroll
        for (int j = 0; j < 8; j++) {
            const int w0 = s_ws[j];
            float2 a00 = *(const float2*)(r0 + w0);
            float2 a01 = *(const float2*)(r0 + w0 + CCH);
            float2 a10 = *(const float2*)(r0 + w0 + FWC);
            float2 a11 = *(const float2*)(r0 + w0 + FWC + CCH);
            float wf = s_wf[j];
            float m  = hm * s_wm[j];
            float tx = a00.x + (a01.x - a00.x) * wf;
            float ty = a00.y + (a01.y - a00.y) * wf;
            float bx = a10.x + (a11.x - a10.x) * wf;
            float by = a10.y + (a11.y - a10.y) * wf;
            cur[j].x = (tx + (bx - tx) * hf) * m;
            cur[j].y = (ty + (by - ty) * hf) * m;
        }

        if (k > 0) {
            int rb = (i - 1) * 7;
            #pragma unroll
            for (int j = 0; j < 7; j++) {
                s_out[c0 * 49 + rb + j] =
                    0.25f * (prev[j].x + prev[j+1].x + cur[j].x + cur[j+1].x);
                s_out[(c0 + 1) * 49 + rb + j] =
                    0.25f * (prev[j].y + prev[j+1].y + cur[j].y + cur[j+1].y);
            }
        }
        #pragma unroll
        for (int j = 0; j < 8; j++) prev[j] = cur[j];
    }
}

// ---------------------------------------------------------------------------
// Kernel B: one 128-thread block per (roi, channel-half).
// 64 float2-threads (=128 channels) x 2 row-groups.
//   g0: sample rows 0..4 -> pooled rows 0..3
//   g1: sample rows 4..7 -> pooled rows 4..6 (row 4 gathered twice)
// float2 gathers halve the LDG instruction count -> LSU-issue floor 63->32us.
// Output staged [128][49] in smem == linear layout of this half's region ->
// coalesced float4 flush. launch_bounds(128,6) caps regs at 85 (no spill
// risk; round-2 showed spills are catastrophic).
// ---------------------------------------------------------------------------
__global__ __launch_bounds__(128, 6) void roi_kernel(
    const float* __restrict__ rois,
    const int*   __restrict__ bids,
    float*       __restrict__ out)
{
    extern __shared__ float s_out[];   // [128][49]
    __shared__ int   s_ws[8], s_hs[8];
    __shared__ float s_wf[8], s_hf[8], s_wm[8], s_hm[8];

    const int bx   = blockIdx.x;
    const int r    = bx >> 1;
    const int half = bx & 1;
    const int t    = threadIdx.x;
    const int p    = t & 63;           // float2 channel-pair index
    const int g    = t >> 6;           // warps 0-1: g=0, warps 2-3: g=1

    if (t < 8) {
        float x1 = rois[r*4 + 0] * 0.0625f;
        float x2 = rois[r*4 + 2] * 0.0625f;
        float bw = fmaxf(x2 - x1 + 1.0f, 0.0f) * (1.0f / 7.0f);
        float w  = x1 + (float)t * bw;
        s_wm[t]  = (w >= 0.0f && w < (float)FW) ? 1.0f : 0.0f;
        float wsf = fminf(fmaxf(floorf(w), 0.0f), (float)(FW - 2));
        s_ws[t]  = (int)wsf * CCH;     // pre-scaled column offset (floats)
        s_wf[t]  = w - wsf;
    } else if (t < 16) {
        int i = t & 7;
        float y1 = rois[r*4 + 1] * 0.0625f;
        float y2 = rois[r*4 + 3] * 0.0625f;
        float bh = fmaxf(y2 - y1 + 1.0f, 0.0f) * (1.0f / 7.0f);
        float h  = y1 + (float)i * bh;
        s_hm[i]  = (h >= 0.0f && h < (float)FH) ? 1.0f : 0.0f;
        float hsf = fminf(fmaxf(floorf(h), 0.0f), (float)(FH - 2));
        s_hs[i]  = (int)hsf;
        s_hf[i]  = h - hsf;
    }
    __syncthreads();

    const int b = bids[r];
    // base of this thread's channel pair (even offset -> 8B aligned)
    const float* fbase = g_nhwc + (size_t)b * HW * CCH + half * HALF_CH + 2 * p;

    if (g == 0)
        process_rows2<5>(0, fbase, 2*p, s_ws, s_hs, s_wf, s_hf, s_wm, s_hm, s_out);
    else
        process_rows2<4>(4, fbase, 2*p, s_ws, s_hs, s_wf, s_hf, s_wm, s_hm, s_out);

    __syncthreads();

    // Coalesced flush: this half's output region is linear in global memory.
    float4*       op = (float4*)(out + (size_t)r * (CCH*49) + half * HALF_OUT);
    const float4* sp = (const float4*)s_out;
    #pragma unroll
    for (int m = t; m < HALF_OUT / 4; m += 128)
        op[m] = sp[m];
}

// ---------------------------------------------------------------------------
extern "C" void kernel_launch(void* const* d_in, const int* in_sizes, int n_in,
                              void* d_out, int out_size) {
    const float* features = (const float*)d_in[0];
    const float* rois     = (const float*)d_in[1];
    const int*   bids     = (const int*)d_in[2];
    float*       out      = (float*)d_out;

    dim3 tgrid(HW / 32, CCH / 32, NBATCH);   // (475, 8, 4)
    transpose_kernel<<<tgrid, dim3(32, 8)>>>(features);

    cudaFuncSetAttribute(roi_kernel,
                         cudaFuncAttributeMaxDynamicSharedMemorySize,
                         SMEM_BYTES);
    roi_kernel<<<NROI * 2, 128, SMEM_BYTES>>>(rois, bids, out);
}

// round 5
// speedup vs baseline: 1.0489x; 1.0489x over previous
#include <cuda_runtime.h>

#define NBATCH 4
#define CCH 256
#define FH 100
#define FW 152
#define HW (FH*FW)           // 15200
#define FWC (FW*CCH)         // 38912
#define NROI 4000
#define HALF_CH 128
#define HALF_OUT (HALF_CH*49)      // 6272 floats, linear 16B-aligned region
#define SMEM_BYTES (HALF_OUT*4)    // 25088 B

// NHWC scratch (device global: allocation-free scratch per harness rules)
__device__ float g_nhwc[NBATCH * HW * CCH];

// ---------------------------------------------------------------------------
// Kernel A: NCHW -> NHWC transpose (per batch: [256, 15200] transpose),
// 32x32 smem tiles, both phases fully coalesced.
// ---------------------------------------------------------------------------
__global__ void transpose_kernel(const float* __restrict__ in) {
    __shared__ float tile[32][33];
    int b   = blockIdx.z;
    int hw0 = blockIdx.x * 32;
    int c0  = blockIdx.y * 32;

    const float* src = in + (size_t)b * CCH * HW;
    #pragma unroll
    for (int r = threadIdx.y; r < 32; r += 8)
        tile[r][threadIdx.x] = src[(size_t)(c0 + r) * HW + (hw0 + threadIdx.x)];
    __syncthreads();

    float* dst = g_nhwc + (size_t)b * HW * CCH;
    #pragma unroll
    for (int r = threadIdx.y; r < 32; r += 8)
        dst[(size_t)(hw0 + r) * CCH + (c0 + threadIdx.x)] = tile[threadIdx.x][r];
}

// ---------------------------------------------------------------------------
// Row-group body: scalar gathers, horizontal-sum rolling carry.
// After gathering a sample row, immediately reduce to 7 horizontal pair-sums;
// pooled row = 0.25 * (hprev + hcur). Peak live floats ~15 (vs 24 with
// prev[8]/cur[8]) so the 48-reg cap leaves room for load batching.
// ---------------------------------------------------------------------------
template<int NR>
__device__ __forceinline__ void process_rows(
    int i0, const float* __restrict__ fbase, int c,
    const int* s_ws, const int* s_hs,
    const float* s_wf, const float* s_hf,
    const float* s_wm, const float* s_hm,
    float* s_out)
{
    float hprev[7];
    #pragma unroll
    for (int k = 0; k < NR; ++k) {
        const int i = i0 + k;
        const float* r0 = fbase + s_hs[i] * FWC;
        const float hf = s_hf[i];
        const float hm = s_hm[i];

        float cur[8];
        #pragma unroll
        for (int j = 0; j < 8; j++) {
            const int w0 = s_ws[j];
            float a00 = r0[w0];
            float a01 = r0[w0 + CCH];
            float a10 = r0[w0 + FWC];
            float a11 = r0[w0 + FWC + CCH];
            float wf  = s_wf[j];
            float top = a00 + (a01 - a00) * wf;
            float bot = a10 + (a11 - a10) * wf;
            cur[j] = (top + (bot - top) * hf) * (hm * s_wm[j]);
        }

        float hcur[7];
        #pragma unroll
        for (int j = 0; j < 7; j++) hcur[j] = cur[j] + cur[j+1];

        if (k > 0) {
            int rb = c * 49 + (i - 1) * 7;
            #pragma unroll
            for (int j = 0; j < 7; j++)
                s_out[rb + j] = 0.25f * (hprev[j] + hcur[j]);
        }
        #pragma unroll
        for (int j = 0; j < 7; j++) hprev[j] = hcur[j];
    }
}

// ---------------------------------------------------------------------------
// Kernel B: one 256-thread block per (roi, channel-half).
// 128 channels x 2 row-groups (g0: rows 0..4 -> pooled 0..3; g1: rows 4..7
// -> pooled 4..6, row 4 gathered twice). Scalar gathers (round-4 showed
// float2 buys nothing: same wavefront count, fewer warps). Output staged
// [128][49] in smem == linear layout of this half's region -> float4 flush.
// launch_bounds(256,5): 48-reg cap -> 5 CTAs/SM = 40 warps. (32 regs spills
// catastrophically, 64 regs caps at 4 CTAs; 48 is the untried middle.)
// ---------------------------------------------------------------------------
__global__ __launch_bounds__(256, 5) void roi_kernel(
    const float* __restrict__ rois,
    const int*   __restrict__ bids,
    float*       __restrict__ out)
{
    extern __shared__ float s_out[];   // [128][49]
    __shared__ int   s_ws[8], s_hs[8];
    __shared__ float s_wf[8], s_hf[8], s_wm[8], s_hm[8];

    const int bx   = blockIdx.x;
    const int r    = bx >> 1;
    const int half = bx & 1;
    const int t    = threadIdx.x;
    const int c    = t & (HALF_CH - 1);
    const int g    = t >> 7;           // warps 0-3: g=0, warps 4-7: g=1

    if (t < 8) {
        float x1 = rois[r*4 + 0] * 0.0625f;
        float x2 = rois[r*4 + 2] * 0.0625f;
        float bw = fmaxf(x2 - x1 + 1.0f, 0.0f) * (1.0f / 7.0f);
        float w  = x1 + (float)t * bw;
        s_wm[t]  = (w >= 0.0f && w < (float)FW) ? 1.0f : 0.0f;
        float wsf = fminf(fmaxf(floorf(w), 0.0f), (float)(FW - 2));
        s_ws[t]  = (int)wsf * CCH;     // pre-scaled column offset (floats)
        s_wf[t]  = w - wsf;
    } else if (t < 16) {
        int i = t & 7;
        float y1 = rois[r*4 + 1] * 0.0625f;
        float y2 = rois[r*4 + 3] * 0.0625f;
        float bh = fmaxf(y2 - y1 + 1.0f, 0.0f) * (1.0f / 7.0f);
        float h  = y1 + (float)i * bh;
        s_hm[i]  = (h >= 0.0f && h < (float)FH) ? 1.0f : 0.0f;
        float hsf = fminf(fmaxf(floorf(h), 0.0f), (float)(FH - 2));
        s_hs[i]  = (int)hsf;
        s_hf[i]  = h - hsf;
    }
    __syncthreads();

    const int b = bids[r];
    const float* fbase = g_nhwc + (size_t)b * HW * CCH + half * HALF_CH + c;

    if (g == 0)
        process_rows<5>(0, fbase, c, s_ws, s_hs, s_wf, s_hf, s_wm, s_hm, s_out);
    else
        process_rows<4>(4, fbase, c, s_ws, s_hs, s_wf, s_hf, s_wm, s_hm, s_out);

    __syncthreads();

    // Coalesced flush: this half's output region is linear in global memory.
    float4*       op = (float4*)(out + (size_t)r * (CCH*49) + half * HALF_OUT);
    const float4* sp = (const float4*)s_out;
    #pragma unroll
    for (int m = t; m < HALF_OUT / 4; m += 256)
        op[m] = sp[m];
}

// ---------------------------------------------------------------------------
extern "C" void kernel_launch(void* const* d_in, const int* in_sizes, int n_in,
                              void* d_out, int out_size) {
    const float* features = (const float*)d_in[0];
    const float* rois     = (const float*)d_in[1];
    const int*   bids     = (const int*)d_in[2];
    float*       out      = (float*)d_out;

    dim3 tgrid(HW / 32, CCH / 32, NBATCH);   // (475, 8, 4)
    transpose_kernel<<<tgrid, dim3(32, 8)>>>(features);

    cudaFuncSetAttribute(roi_kernel,
                         cudaFuncAttributeMaxDynamicSharedMemorySize,
                         SMEM_BYTES);
    roi_kernel<<<NROI * 2, 256, SMEM_BYTES>>>(rois, bids, out);
}

// round 6
// speedup vs baseline: 1.1723x; 1.1176x over previous
#include <cuda_runtime.h>

#define NBATCH 4
#define CCH 256
#define FH 100
#define FW 152
#define HW (FH*FW)           // 15200
#define FWC (FW*CCH)         // 38912
#define NROI 4000
#define OUT_PER_ROI (CCH*49)       // 12544 floats, linear
#define SMEM_BYTES (OUT_PER_ROI*4) // 50176 B -> 4 CTAs/SM

// NHWC scratch (device global: allocation-free scratch per harness rules)
__device__ float g_nhwc[NBATCH * HW * CCH];

// ---------------------------------------------------------------------------
// Kernel A: NCHW -> NHWC transpose (per batch: [256, 15200] transpose),
// 32x32 smem tiles, both phases fully coalesced.
// ---------------------------------------------------------------------------
__global__ void transpose_kernel(const float* __restrict__ in) {
    __shared__ float tile[32][33];
    int b   = blockIdx.z;
    int hw0 = blockIdx.x * 32;
    int c0  = blockIdx.y * 32;

    const float* src = in + (size_t)b * CCH * HW;
    #pragma unroll
    for (int r = threadIdx.y; r < 32; r += 8)
        tile[r][threadIdx.x] = src[(size_t)(c0 + r) * HW + (hw0 + threadIdx.x)];
    __syncthreads();

    float* dst = g_nhwc + (size_t)b * HW * CCH;
    #pragma unroll
    for (int r = threadIdx.y; r < 32; r += 8)
        dst[(size_t)(hw0 + r) * CCH + (c0 + threadIdx.x)] = tile[threadIdx.x][r];
}

// ---------------------------------------------------------------------------
// Row-group body: float2 gathers (2 consecutive channels / thread),
// horizontal-sum rolling carry (live set ~30 floats -> fits 64-reg cap).
// ---------------------------------------------------------------------------
template<int NR>
__device__ __forceinline__ void process_rows2(
    int i0, const float* __restrict__ fbase, int c0,
    const int* s_ws, const int* s_hs,
    const float* s_wf, const float* s_hf,
    const float* s_wm, const float* s_hm,
    float* s_out)
{
    float2 hprev[7];
    #pragma unroll
    for (int k = 0; k < NR; ++k) {
        const int i = i0 + k;
        const float* r0 = fbase + s_hs[i] * FWC;
        const float hf = s_hf[i];
        const float hm = s_hm[i];

        float2 cur[8];
        #pragma unroll
        for (int j = 0; j < 8; j++) {
            const int w0 = s_ws[j];
            float2 a00 = *(const float2*)(r0 + w0);
            float2 a01 = *(const float2*)(r0 + w0 + CCH);
            float2 a10 = *(const float2*)(r0 + w0 + FWC);
            float2 a11 = *(const float2*)(r0 + w0 + FWC + CCH);
            float wf = s_wf[j];
            float m  = hm * s_wm[j];
            float tx = a00.x + (a01.x - a00.x) * wf;
            float ty = a00.y + (a01.y - a00.y) * wf;
            float bx = a10.x + (a11.x - a10.x) * wf;
            float by = a10.y + (a11.y - a10.y) * wf;
            cur[j].x = (tx + (bx - tx) * hf) * m;
            cur[j].y = (ty + (by - ty) * hf) * m;
        }

        float2 hcur[7];
        #pragma unroll
        for (int j = 0; j < 7; j++) {
            hcur[j].x = cur[j].x + cur[j+1].x;
            hcur[j].y = cur[j].y + cur[j+1].y;
        }

        if (k > 0) {
            int rb = (i - 1) * 7;
            #pragma unroll
            for (int j = 0; j < 7; j++) {
                s_out[c0 * 49 + rb + j]       = 0.25f * (hprev[j].x + hcur[j].x);
                s_out[(c0 + 1) * 49 + rb + j] = 0.25f * (hprev[j].y + hcur[j].y);
            }
        }
        #pragma unroll
        for (int j = 0; j < 7; j++) hprev[j] = hcur[j];
    }
}

// ---------------------------------------------------------------------------
// Kernel B: one 256-thread block per roi (full 256 channels).
// 128 float2-threads x 2 row-groups (g0 rows 0..4 -> pooled 0..3,
// g1 rows 4..7 -> pooled 4..6; row 4 gathered twice).
// float2 halves the warp-LDG count (LSU floor 63 -> 31us); the 64-reg cap +
// 50KB smem give 4 CTAs/SM = 32 warps — round-4's float2 lost ONLY because
// it ran at 24 warps. Output staged [256][49] in smem = exactly the roi's
// linear output block -> coalesced float4 flush.
// ---------------------------------------------------------------------------
__global__ __launch_bounds__(256, 4) void roi_kernel(
    const float* __restrict__ rois,
    const int*   __restrict__ bids,
    float*       __restrict__ out)
{
    extern __shared__ float s_out[];   // [256][49]
    __shared__ int   s_ws[8], s_hs[8];
    __shared__ float s_wf[8], s_hf[8], s_wm[8], s_hm[8];

    const int r = blockIdx.x;
    const int t = threadIdx.x;
    const int p = t & 127;             // channel-pair index (channels 2p, 2p+1)
    const int g = t >> 7;              // warps 0-3: g=0, warps 4-7: g=1

    if (t < 8) {
        float x1 = rois[r*4 + 0] * 0.0625f;
        float x2 = rois[r*4 + 2] * 0.0625f;
        float bw = fmaxf(x2 - x1 + 1.0f, 0.0f) * (1.0f / 7.0f);
        float w  = x1 + (float)t * bw;
        s_wm[t]  = (w >= 0.0f && w < (float)FW) ? 1.0f : 0.0f;
        float wsf = fminf(fmaxf(floorf(w), 0.0f), (float)(FW - 2));
        s_ws[t]  = (int)wsf * CCH;     // pre-scaled column offset (floats)
        s_wf[t]  = w - wsf;
    } else if (t < 16) {
        int i = t & 7;
        float y1 = rois[r*4 + 1] * 0.0625f;
        float y2 = rois[r*4 + 3] * 0.0625f;
        float bh = fmaxf(y2 - y1 + 1.0f, 0.0f) * (1.0f / 7.0f);
        float h  = y1 + (float)i * bh;
        s_hm[i]  = (h >= 0.0f && h < (float)FH) ? 1.0f : 0.0f;
        float hsf = fminf(fmaxf(floorf(h), 0.0f), (float)(FH - 2));
        s_hs[i]  = (int)hsf;
        s_hf[i]  = h - hsf;
    }
    __syncthreads();

    const int b = bids[r];
    // base of this thread's channel pair (even float offset -> 8B aligned)
    const float* fbase = g_nhwc + (size_t)b * HW * CCH + 2 * p;

    if (g == 0)
        process_rows2<5>(0, fbase, 2*p, s_ws, s_hs, s_wf, s_hf, s_wm, s_hm, s_out);
    else
        process_rows2<4>(4, fbase, 2*p, s_ws, s_hs, s_wf, s_hf, s_wm, s_hm, s_out);

    __syncthreads();

    // Coalesced flush: the roi's output block is linear in global memory.
    float4*       op = (float4*)(out + (size_t)r * OUT_PER_ROI);
    const float4* sp = (const float4*)s_out;
    #pragma unroll
    for (int m = t; m < OUT_PER_ROI / 4; m += 256)
        op[m] = sp[m];
}

// ---------------------------------------------------------------------------
extern "C" void kernel_launch(void* const* d_in, const int* in_sizes, int n_in,
                              void* d_out, int out_size) {
    const float* features = (const float*)d_in[0];
    const float* rois     = (const float*)d_in[1];
    const int*   bids     = (const int*)d_in[2];
    float*       out      = (float*)d_out;

    dim3 tgrid(HW / 32, CCH / 32, NBATCH);   // (475, 8, 4)
    transpose_kernel<<<tgrid, dim3(32, 8)>>>(features);

    cudaFuncSetAttribute(roi_kernel,
                         cudaFuncAttributeMaxDynamicSharedMemorySize,
                         SMEM_BYTES);
    roi_kernel<<<NROI, 256, SMEM_BYTES>>>(rois, bids, out);
}